// round 1
// baseline (speedup 1.0000x reference)
#include <cuda_runtime.h>
#include <math.h>

#define NN 50000
#define NE 800000

// Scratch (static device allocations are permitted)
__device__ float g_s1 [NN * 64];   // s @ W1_s / 8
__device__ float g_v1 [NN * 96];   // v . W1_v / sqrt(32), layout [n][u][i]
__device__ float g_ags[NN * 64];   // scalar aggregate
__device__ float g_agv[NN * 96];   // vector aggregate [n][u][i]

__device__ __forceinline__ float sigmoidf_(float x) { return 1.0f / (1.0f + __expf(-x)); }
__device__ __forceinline__ float siluf_(float x)    { return x / (1.0f + __expf(-x)); }

// ---------------------------------------------------------------------------
// Kernel 1: node pre-transform  (one warp per node)  + zero the aggregates
// ---------------------------------------------------------------------------
__global__ void __launch_bounds__(256) k_node_pre(
    const float* __restrict__ feats,
    const float* __restrict__ W1s,
    const float* __restrict__ W1v)
{
    __shared__ float sW1s[64 * 64];
    __shared__ float sW1v[32 * 32];
    __shared__ float stage[8][160];

    int tid = threadIdx.x;

    // zero aggregates (grid covers it: 6250*256 = 1.6M threads)
    {
        int gidx = blockIdx.x * 256 + tid;
        float4 z = make_float4(0.f, 0.f, 0.f, 0.f);
        if (gidx < NN * 16) ((float4*)g_ags)[gidx] = z;   // 800k float4
        if (gidx < NN * 24) ((float4*)g_agv)[gidx] = z;   // 1.2M float4
    }

    for (int i = tid; i < 4096; i += 256) sW1s[i] = W1s[i];
    for (int i = tid; i < 1024; i += 256) sW1v[i] = W1v[i];
    __syncthreads();

    int warp = tid >> 5, lane = tid & 31;
    int n = blockIdx.x * 8 + warp;
    if (n >= NN) return;

    #pragma unroll
    for (int j = 0; j < 5; j++)
        stage[warp][lane * 5 + j] = feats[n * 160 + lane * 5 + j];
    __syncwarp();

    // s1 columns lane, lane+32
    float a0 = 0.f, a1 = 0.f;
    #pragma unroll 8
    for (int u = 0; u < 64; u++) {
        float su = stage[warp][u];
        a0 += su * sW1s[u * 64 + lane];
        a1 += su * sW1s[u * 64 + 32 + lane];
    }
    g_s1[n * 64 + lane]      = a0 * 0.125f;
    g_s1[n * 64 + 32 + lane] = a1 * 0.125f;

    // v1 column lane (3 components)
    float b0 = 0.f, b1 = 0.f, b2 = 0.f;
    #pragma unroll 8
    for (int u = 0; u < 32; u++) {
        float wv = sW1v[u * 32 + lane];
        const float* vp = &stage[warp][64 + u * 3];
        b0 += vp[0] * wv; b1 += vp[1] * wv; b2 += vp[2] * wv;
    }
    const float sv = 0.17677669529663687f; // 1/sqrt(32)
    g_v1[n * 96 + lane * 3 + 0] = b0 * sv;
    g_v1[n * 96 + lane * 3 + 1] = b1 * sv;
    g_v1[n * 96 + lane * 3 + 2] = b2 * sv;
}

// ---------------------------------------------------------------------------
// Kernel 2: edge messages.  One warp handles a group of 4 edges so the
// W2 smem weight loads are amortized 4x in the matvec loop.
// ---------------------------------------------------------------------------
#define K2_WARPS 4
#define K2_EPW   4

__global__ void __launch_bounds__(128) k_edge(
    const float* __restrict__ ea,   // edge_attrs  (E,4)
    const float* __restrict__ emb,  // edge_embedding (E,8)
    const float* __restrict__ mw0,  // (8,8)
    const float* __restrict__ mw1,  // (8,192)
    const float* __restrict__ W2s,  // (96,96)
    const float* __restrict__ W2v,  // (96,32)
    const int*   __restrict__ ei)   // (2,E)
{
    extern __shared__ float sm[];
    float* sW2s = sm;                 // 9216
    float* sW2v = sm + 9216;          // 3072
    float* sMw0 = sm + 12288;         // 64
    float* sMw1 = sm + 12352;         // 1536
    float* sMS  = sm + 13888;         // 4 warps * 4 edges * 96
    float* sMV  = sm + 15424;         // 4 warps * 4 edges * 96 float4

    int tid = threadIdx.x;
    for (int i = tid; i < 9216; i += 128) sW2s[i] = W2s[i];
    for (int i = tid; i < 3072; i += 128) sW2v[i] = W2v[i];
    for (int i = tid; i < 64;   i += 128) sMw0[i] = mw0[i];
    for (int i = tid; i < 1536; i += 128) sMw1[i] = mw1[i];
    __syncthreads();

    int warp = tid >> 5, lane = tid & 31;
    float*  ms = sMS + warp * (K2_EPW * 96);
    float4* mv = ((float4*)sMV) + warp * (K2_EPW * 96);

    const float is8  = 0.35355339059327373f;  // 1/sqrt(8)
    const float is96 = 0.10206207261596575f;  // 1/sqrt(96)
    const float is3  = 0.57735026918962576f;  // 1/sqrt(3)

    long long stride = (long long)gridDim.x * K2_WARPS * K2_EPW;
    for (long long e0 = (long long)(blockIdx.x * K2_WARPS + warp) * K2_EPW;
         e0 < NE; e0 += stride) {

        int dsts[K2_EPW];

        // ---- phase 1: build messages for 4 edges ----
        #pragma unroll
        for (int j = 0; j < K2_EPW; j++) {
            int e = (int)e0 + j;
            int src = ei[e];
            dsts[j] = ei[NE + e];

            float4 yv = ((const float4*)ea)[e];
            float Y0 = yv.x, yx = yv.y, yy = yv.z, yz = yv.w;

            float h[8];
            {
                float4 em0 = ((const float4*)emb)[e * 2 + 0];
                float4 em1 = ((const float4*)emb)[e * 2 + 1];
                float em[8] = {em0.x, em0.y, em0.z, em0.w, em1.x, em1.y, em1.z, em1.w};
                #pragma unroll
                for (int q = 0; q < 8; q++) {
                    float t = 0.f;
                    #pragma unroll
                    for (int k = 0; k < 8; k++) t += em[k] * sMw0[k * 8 + q];
                    h[q] = siluf_(t * is8);
                }
            }
            float wa = 0.f, wb = 0.f, wc = 0.f, wd = 0.f, we = 0.f, wf = 0.f;
            #pragma unroll
            for (int q = 0; q < 8; q++) {
                float hq = h[q]; const float* r = &sMw1[q * 192];
                wa += hq * r[lane];       wb += hq * r[32 + lane];
                wc += hq * r[64 + lane];  wd += hq * r[96 + lane];
                we += hq * r[128 + lane]; wf += hq * r[160 + lane];
            }
            wa *= is8; wb *= is8; wc *= is8; wd *= is8; we *= is8; wf *= is8;

            float se0 = g_s1[src * 64 + lane];
            float se1 = g_s1[src * 64 + 32 + lane];
            const float* vp = &g_v1[src * 96 + lane * 3];
            float vx = vp[0], vy = vp[1], vz = vp[2];

            float*  msj = ms + j * 96;
            float4* mvj = mv + j * 96;
            msj[lane]      = wa * se0 * Y0;
            msj[32 + lane] = wb * se1 * Y0;
            msj[64 + lane] = wf * (vx * yx + vy * yy + vz * yz) * is3;
            float p0 = wc * se0, p1 = wd * se1, q0 = we * Y0;
            mvj[lane]      = make_float4(p0 * yx, p0 * yy, p0 * yz, 0.f);
            mvj[32 + lane] = make_float4(p1 * yx, p1 * yy, p1 * yz, 0.f);
            mvj[64 + lane] = make_float4(q0 * vx, q0 * vy, q0 * vz, 0.f);
        }
        __syncwarp();

        // ---- phase 2: fused matvecs, weights amortized over 4 edges ----
        float as[K2_EPW][3];
        float4 av[K2_EPW];
        #pragma unroll
        for (int j = 0; j < K2_EPW; j++) {
            as[j][0] = as[j][1] = as[j][2] = 0.f;
            av[j] = make_float4(0.f, 0.f, 0.f, 0.f);
        }
        #pragma unroll 4
        for (int u = 0; u < 96; u++) {
            float w0 = sW2s[u * 96 + lane];
            float w1 = sW2s[u * 96 + 32 + lane];
            float w2 = sW2s[u * 96 + 64 + lane];
            float wv = sW2v[u * 32 + lane];
            #pragma unroll
            for (int j = 0; j < K2_EPW; j++) {
                float  m = ms[j * 96 + u];
                float4 q = mv[j * 96 + u];
                as[j][0] += m * w0; as[j][1] += m * w1; as[j][2] += m * w2;
                av[j].x += q.x * wv; av[j].y += q.y * wv; av[j].z += q.z * wv;
            }
        }
        __syncwarp();

        // ---- phase 3: gate + scatter ----
        #pragma unroll
        for (int j = 0; j < K2_EPW; j++) {
            int dst = dsts[j];
            float m0 = as[j][0] * is96, m1 = as[j][1] * is96, m2 = as[j][2] * is96;
            float g0 = siluf_(m0) * 0.25f;
            float g1 = siluf_(m1) * 0.25f;
            float gate = sigmoidf_(m2) * 0.25f;
            atomicAdd(&g_ags[dst * 64 + lane],          g0);
            atomicAdd(&g_ags[dst * 64 + 32 + lane],     g1);
            atomicAdd(&g_agv[dst * 96 + lane * 3 + 0], av[j].x * is96 * gate);
            atomicAdd(&g_agv[dst * 96 + lane * 3 + 1], av[j].y * is96 * gate);
            atomicAdd(&g_agv[dst * 96 + lane * 3 + 2], av[j].z * is96 * gate);
        }
    }
}

// ---------------------------------------------------------------------------
// Kernel 3: node post.  8 nodes per block, 96 threads (one output column each);
// SC tensors streamed from L2, amortized over the 8 nodes via smem coefs.
// ---------------------------------------------------------------------------
__global__ void __launch_bounds__(96) k_node_post(
    const float* __restrict__ feats,
    const float* __restrict__ attrs,
    const float* __restrict__ Us,   // (64,16)
    const float* __restrict__ Uv,   // (32,16)
    const float* __restrict__ W3s,  // (64,96)
    const float* __restrict__ W3v,  // (32,32)
    const float* __restrict__ SCs,  // (64,16,96)
    const float* __restrict__ SCv,  // (32,16,32)
    float* __restrict__ out)
{
    extern __shared__ float sm[];
    float* cS     = sm;          // 8*1024
    float* cV     = sm + 8192;   // 8*3*512
    float* us_s   = sm + 20480;  // 8*64
    float* uv_s   = sm + 20992;  // 8*96
    float* attr_s = sm + 21760;  // 8*16
    float* sS     = sm + 21888;  // 8*64
    float* sV     = sm + 22400;  // 8*96
    float* gate_s = sm + 23168;  // 8*32
    // total 23424 floats = 93696 B

    int tid = threadIdx.x;
    int nbase = blockIdx.x * 8;

    for (int i = tid; i < 8 * 160; i += 96) {
        int t = i / 160, c = i % 160;
        float v = feats[(nbase + t) * 160 + c];
        if (c < 64) sS[t * 64 + c] = v; else sV[t * 96 + (c - 64)] = v;
    }
    for (int i = tid; i < 128; i += 96) attr_s[i] = attrs[nbase * 16 + i];
    __syncthreads();

    // outer-product coefficients
    for (int i = tid; i < 8192; i += 96) {
        int t = i >> 10, k = i & 1023, u = k >> 4, v = k & 15;
        cS[i] = sS[t * 64 + u] * attr_s[t * 16 + v];
    }
    for (int i = tid; i < 12288; i += 96) {
        int t = i / 1536, r = i % 1536, ii = r / 512, k = r % 512;
        int u = k >> 4, v = k & 15;
        cV[i] = sV[t * 96 + u * 3 + ii] * attr_s[t * 16 + v];
    }

    // us, uv (gated aggregates)
    for (int i = tid; i < 512; i += 96) {
        int t = i >> 6, u = i & 63;
        float d = 0.f;
        #pragma unroll
        for (int v = 0; v < 16; v++) d += attr_s[t * 16 + v] * Us[u * 16 + v];
        us_s[i] = g_ags[(nbase + t) * 64 + u] * d * 0.25f;
    }
    for (int i = tid; i < 256; i += 96) {
        int t = i >> 5, u = i & 31;
        float d = 0.f;
        #pragma unroll
        for (int v = 0; v < 16; v++) d += attr_s[t * 16 + v] * Uv[u * 16 + v];
        d *= 0.25f;
        #pragma unroll
        for (int ii = 0; ii < 3; ii++)
            uv_s[t * 96 + u * 3 + ii] = g_agv[(nbase + t) * 96 + u * 3 + ii] * d;
    }
    __syncthreads();

    // ---- ts, one column w = tid per thread, 8 nodes ----
    int w = tid;
    float acc1[8], acc2[8];
    #pragma unroll
    for (int t = 0; t < 8; t++) { acc1[t] = 0.f; acc2[t] = 0.f; }
    #pragma unroll 4
    for (int u = 0; u < 64; u++) {
        float wt = W3s[u * 96 + w];
        #pragma unroll
        for (int t = 0; t < 8; t++) acc1[t] += us_s[t * 64 + u] * wt;
    }
    #pragma unroll 4
    for (int k = 0; k < 1024; k++) {
        float c = SCs[k * 96 + w];
        #pragma unroll
        for (int t = 0; t < 8; t++) acc2[t] += cS[t * 1024 + k] * c;
    }
    float ts[8];
    #pragma unroll
    for (int t = 0; t < 8; t++) ts[t] = acc1[t] * 0.125f + acc2[t] * 0.03125f;

    if (w < 64) {
        #pragma unroll
        for (int t = 0; t < 8; t++)
            out[(nbase + t) * 160 + w] = siluf_(ts[t]);
    } else {
        #pragma unroll
        for (int t = 0; t < 8; t++)
            gate_s[t * 32 + (w - 64)] = sigmoidf_(ts[t]);
    }
    __syncthreads();

    // ---- tv: column (wv = tid%32, component iv = tid/32) ----
    int wv = tid & 31, iv = tid >> 5;
    float a1[8], a2[8];
    #pragma unroll
    for (int t = 0; t < 8; t++) { a1[t] = 0.f; a2[t] = 0.f; }
    #pragma unroll 4
    for (int u = 0; u < 32; u++) {
        float wt = W3v[u * 32 + wv];
        #pragma unroll
        for (int t = 0; t < 8; t++) a1[t] += uv_s[t * 96 + u * 3 + iv] * wt;
    }
    #pragma unroll 4
    for (int k = 0; k < 512; k++) {
        float c = SCv[k * 32 + wv];
        #pragma unroll
        for (int t = 0; t < 8; t++) a2[t] += cV[(t * 3 + iv) * 512 + k] * c;
    }
    const float isv  = 0.17677669529663687f;  // 1/sqrt(32)
    const float isvn = 0.044194173824159220f; // 1/sqrt(512)
    #pragma unroll
    for (int t = 0; t < 8; t++) {
        float tv = a1[t] * isv + a2[t] * isvn;
        out[(nbase + t) * 160 + 64 + wv * 3 + iv] = tv * gate_s[t * 32 + wv];
    }
}

// ---------------------------------------------------------------------------
extern "C" void kernel_launch(void* const* d_in, const int* in_sizes, int n_in,
                              void* d_out, int out_size)
{
    const float* node_feats = (const float*)d_in[0];
    const float* node_attrs = (const float*)d_in[1];
    const float* edge_attrs = (const float*)d_in[2];
    const float* edge_emb   = (const float*)d_in[3];
    const float* W1s        = (const float*)d_in[4];
    const float* W1v        = (const float*)d_in[5];
    const float* mw0        = (const float*)d_in[6];
    const float* mw1        = (const float*)d_in[7];
    const float* W2s        = (const float*)d_in[8];
    const float* W2v        = (const float*)d_in[9];
    const float* Us         = (const float*)d_in[10];
    const float* Uv         = (const float*)d_in[11];
    const float* W3s        = (const float*)d_in[12];
    const float* W3v        = (const float*)d_in[13];
    const float* SCs        = (const float*)d_in[14];
    const float* SCv        = (const float*)d_in[15];
    const int*   ei         = (const int*)  d_in[16];
    float* out = (float*)d_out;

    k_node_pre<<<6250, 256>>>(node_feats, W1s, W1v);

    cudaFuncSetAttribute(k_edge, cudaFuncAttributeMaxDynamicSharedMemorySize, 87040);
    k_edge<<<592, 128, 86272>>>(edge_attrs, edge_emb, mw0, mw1, W2s, W2v, ei);

    cudaFuncSetAttribute(k_node_post, cudaFuncAttributeMaxDynamicSharedMemorySize, 94208);
    k_node_post<<<6250, 96, 93696>>>(node_feats, node_attrs, Us, Uv, W3s, W3v,
                                     SCs, SCv, out);
}

// round 3
// speedup vs baseline: 1.0227x; 1.0227x over previous
#include <cuda_runtime.h>
#include <math.h>

#define NN 50000
#define NE 800000

// Scratch (static device allocations are permitted)
__device__ float g_s1 [NN * 64];   // s @ W1_s / 8                  [n][c]
__device__ float g_v1 [NN * 96];   // v . W1_v / sqrt(32)           [n][i*32+u]
__device__ float g_ags[NN * 64];   // scalar aggregate              [n][c]
__device__ float g_agv[NN * 96];   // vector aggregate              [n][i*32+u]

typedef unsigned long long u64;

__device__ __forceinline__ float sigmoidf_(float x) { return 1.0f / (1.0f + __expf(-x)); }
__device__ __forceinline__ float siluf_(float x)    { return x / (1.0f + __expf(-x)); }

// packed f32x2 helpers (Blackwell FFMA2 — only reachable via PTX)
__device__ __forceinline__ u64 pk2(float x) {
    u64 r; asm("mov.b64 %0, {%1, %1};" : "=l"(r) : "f"(x)); return r;
}
__device__ __forceinline__ float2 up2(u64 v) {
    float2 r; asm("mov.b64 {%0, %1}, %2;" : "=f"(r.x), "=f"(r.y) : "l"(v)); return r;
}
__device__ __forceinline__ void ff2(u64& d, u64 a, u64 b) {
    asm("fma.rn.f32x2 %0, %1, %2, %0;" : "+l"(d) : "l"(a), "l"(b));
}
__device__ __forceinline__ void redv4(float* p, float4 v) {
    asm volatile("red.global.add.v4.f32 [%0], {%1,%2,%3,%4};"
                 :: "l"(p), "f"(v.x), "f"(v.y), "f"(v.z), "f"(v.w) : "memory");
}

// ---------------------------------------------------------------------------
// Kernel 1: node pre-transform  (one warp per node)  + zero the aggregates
// ---------------------------------------------------------------------------
__global__ void __launch_bounds__(256) k_node_pre(
    const float* __restrict__ feats,
    const float* __restrict__ W1s,
    const float* __restrict__ W1v)
{
    __shared__ float sW1s[64 * 64];
    __shared__ float sW1v[32 * 32];
    __shared__ float stage[8][160];

    int tid = threadIdx.x;

    // zero aggregates (grid covers it: 6250*256 = 1.6M threads)
    {
        int gidx = blockIdx.x * 256 + tid;
        float4 z = make_float4(0.f, 0.f, 0.f, 0.f);
        if (gidx < NN * 16) ((float4*)g_ags)[gidx] = z;
        if (gidx < NN * 24) ((float4*)g_agv)[gidx] = z;
    }

    for (int i = tid; i < 4096; i += 256) sW1s[i] = W1s[i];
    for (int i = tid; i < 1024; i += 256) sW1v[i] = W1v[i];
    __syncthreads();

    int warp = tid >> 5, lane = tid & 31;
    int n = blockIdx.x * 8 + warp;
    if (n >= NN) return;

    #pragma unroll
    for (int j = 0; j < 5; j++)
        stage[warp][lane * 5 + j] = feats[n * 160 + lane * 5 + j];
    __syncwarp();

    float a0 = 0.f, a1 = 0.f;
    #pragma unroll 8
    for (int u = 0; u < 64; u++) {
        float su = stage[warp][u];
        a0 += su * sW1s[u * 64 + lane];
        a1 += su * sW1s[u * 64 + 32 + lane];
    }
    g_s1[n * 64 + lane]      = a0 * 0.125f;
    g_s1[n * 64 + 32 + lane] = a1 * 0.125f;

    float b0 = 0.f, b1 = 0.f, b2 = 0.f;
    #pragma unroll 8
    for (int u = 0; u < 32; u++) {
        float wv = sW1v[u * 32 + lane];
        const float* vp = &stage[warp][64 + u * 3];
        b0 += vp[0] * wv; b1 += vp[1] * wv; b2 += vp[2] * wv;
    }
    const float sv = 0.17677669529663687f; // 1/sqrt(32)
    g_v1[n * 96 +      lane] = b0 * sv;    // [i*32+u] layout
    g_v1[n * 96 + 32 + lane] = b1 * sv;
    g_v1[n * 96 + 64 + lane] = b2 * sv;
}

// ---------------------------------------------------------------------------
// Kernel 2: edge messages.  6 warps/block, 8 edges/warp, f32x2 packed matvecs.
// ---------------------------------------------------------------------------
#define K2_WARPS 6
#define K2_EPW   8

__global__ void __launch_bounds__(192) k_edge(
    const float* __restrict__ ea,   // edge_attrs  (E,4)
    const float* __restrict__ emb,  // edge_embedding (E,8)
    const float* __restrict__ mw0,  // (8,8)
    const float* __restrict__ mw1,  // (8,192)
    const float* __restrict__ W2s,  // (96,96)
    const float* __restrict__ W2v,  // (96,32)
    const int*   __restrict__ ei)   // (2,E)
{
    extern __shared__ float sm[];
    float* sW2s = sm;                  // 9216
    float* sW2v = sm + 9216;           // 3072
    float* sMw0 = sm + 12288;          // 64
    float* sMw1 = sm + 12352;          // 1536
    float* sStg = sm + 13888;          // 6 warps * 2048
    int*   sDAll  = (int*)(sm + 13888 + 12288);   // 6*8
    float* sY1All = sm + 13888 + 12288 + 48;      // 6*24

    int tid = threadIdx.x;
    for (int i = tid; i < 9216; i += 192) sW2s[i] = W2s[i];
    for (int i = tid; i < 3072; i += 192) sW2v[i] = W2v[i];
    for (int i = tid; i < 64;   i += 192) sMw0[i] = mw0[i];
    for (int i = tid; i < 1536; i += 192) sMw1[i] = mw1[i];
    __syncthreads();

    int warp = tid >> 5, lane = tid & 31;
    float* st  = sStg + warp * 2048;        // A:[0,768) B:[768,1280) C:[1280,2048)
    int*   sD  = sDAll  + warp * 8;
    float* sY1 = sY1All + warp * 24;

    const float is8  = 0.35355339059327373f;  // 1/sqrt(8)
    const float is96 = 0.10206207261596575f;  // 1/sqrt(96)
    const float is3  = 0.57735026918962576f;  // 1/sqrt(3)

    long long stride = (long long)gridDim.x * K2_WARPS * K2_EPW;
    for (long long e0 = (long long)(blockIdx.x * K2_WARPS + warp) * K2_EPW;
         e0 < NE; e0 += stride) {

        // ---- phase 1: build staged messages for 8 edges ----
        #pragma unroll 4
        for (int j = 0; j < K2_EPW; j++) {
            int e = (int)e0 + j;
            int src = ei[e];
            int dst = ei[NE + e];

            float4 yv = ((const float4*)ea)[e];
            float Y0 = yv.x, yx = yv.y, yy = yv.z, yz = yv.w;

            float h[8];
            {
                float4 em0 = ((const float4*)emb)[e * 2 + 0];
                float4 em1 = ((const float4*)emb)[e * 2 + 1];
                float em[8] = {em0.x, em0.y, em0.z, em0.w, em1.x, em1.y, em1.z, em1.w};
                #pragma unroll
                for (int q = 0; q < 8; q++) {
                    float t = 0.f;
                    #pragma unroll
                    for (int k = 0; k < 8; k++) t += em[k] * sMw0[k * 8 + q];
                    h[q] = siluf_(t * is8);
                }
            }
            float wa = 0.f, wb = 0.f, wc = 0.f, wd = 0.f, we = 0.f, wf = 0.f;
            #pragma unroll
            for (int q = 0; q < 8; q++) {
                float hq = h[q]; const float* r = &sMw1[q * 192];
                wa += hq * r[lane];       wb += hq * r[32 + lane];
                wc += hq * r[64 + lane];  wd += hq * r[96 + lane];
                we += hq * r[128 + lane]; wf += hq * r[160 + lane];
            }
            wa *= is8; wb *= is8; wc *= is8; wd *= is8; we *= is8; wf *= is8;

            float se0 = g_s1[src * 64 + lane];
            float se1 = g_s1[src * 64 + 32 + lane];
            float vx  = g_v1[src * 96 +      lane];
            float vy  = g_v1[src * 96 + 32 + lane];
            float vz  = g_v1[src * 96 + 64 + lane];

            // A (ms, 96), B (scalar part of mv, 64), C (vector part of mv, 32x3)
            st[ lane       * 8 + j] = wa * se0 * Y0;
            st[(32 + lane) * 8 + j] = wb * se1 * Y0;
            st[(64 + lane) * 8 + j] = wf * (vx * yx + vy * yy + vz * yz) * is3;
            st[768 +  lane       * 8 + j] = wc * se0;
            st[768 + (32 + lane) * 8 + j] = wd * se1;
            float q0 = we * Y0;
            st[1280 + (lane * 3 + 0) * 8 + j] = q0 * vx;
            st[1280 + (lane * 3 + 1) * 8 + j] = q0 * vy;
            st[1280 + (lane * 3 + 2) * 8 + j] = q0 * vz;

            if (lane == 0) sD[j] = dst;
            if (lane < 3)  sY1[j * 3 + lane] = (lane == 0) ? yx : (lane == 1 ? yy : yz);
        }
        __syncwarp();

        // ---- phase 2: packed-f32x2 matvecs, weights amortized over 8 edges ----
        u64 aS[4][3], aT1[4], aT2[4][3];
        #pragma unroll
        for (int p = 0; p < 4; p++) {
            aS[p][0] = aS[p][1] = aS[p][2] = 0ULL;
            aT1[p] = 0ULL;
            aT2[p][0] = aT2[p][1] = aT2[p][2] = 0ULL;
        }
        const u64* A64 = (const u64*)st;            // [u*4 + p]
        const u64* B64 = (const u64*)(st + 768);
        const u64* C64 = (const u64*)(st + 1280);   // [(u*3+i)*4 + p]

        #pragma unroll 4
        for (int u = 0; u < 96; u++) {
            u64 W0 = pk2(sW2s[u * 96 + lane]);
            u64 W1 = pk2(sW2s[u * 96 + 32 + lane]);
            u64 W2 = pk2(sW2s[u * 96 + 64 + lane]);
            #pragma unroll
            for (int p = 0; p < 4; p++) {
                u64 a = A64[u * 4 + p];
                ff2(aS[p][0], a, W0);
                ff2(aS[p][1], a, W1);
                ff2(aS[p][2], a, W2);
            }
        }
        #pragma unroll 4
        for (int u = 0; u < 64; u++) {
            u64 W = pk2(sW2v[u * 32 + lane]);
            #pragma unroll
            for (int p = 0; p < 4; p++) ff2(aT1[p], B64[u * 4 + p], W);
        }
        #pragma unroll 4
        for (int u = 0; u < 32; u++) {
            u64 W = pk2(sW2v[(64 + u) * 32 + lane]);
            #pragma unroll
            for (int i = 0; i < 3; i++)
                #pragma unroll
                for (int p = 0; p < 4; p++)
                    ff2(aT2[p][i], C64[(u * 3 + i) * 4 + p], W);
        }
        __syncwarp();   // staged message reads done; region reused below

        // ---- phase 3: gate, restage, vector-red scatter ----
        #pragma unroll
        for (int p = 0; p < 4; p++) {
            float2 m0 = up2(aS[p][0]), m1 = up2(aS[p][1]), m2 = up2(aS[p][2]);
            float2 t1 = up2(aT1[p]);
            float2 c0 = up2(aT2[p][0]), c1 = up2(aT2[p][1]), c2 = up2(aT2[p][2]);
            #pragma unroll
            for (int h = 0; h < 2; h++) {
                int j = p * 2 + h;
                float M0 = (h ? m0.y : m0.x) * is96;
                float M1 = (h ? m1.y : m1.x) * is96;
                float M2 = (h ? m2.y : m2.x) * is96;
                float T1 = (h ? t1.y : t1.x) * is96;
                float T20 = (h ? c0.y : c0.x) * is96;
                float T21 = (h ? c1.y : c1.x) * is96;
                float T22 = (h ? c2.y : c2.x) * is96;
                float y1x = sY1[j * 3 + 0];
                float y1y = sY1[j * 3 + 1];
                float y1z = sY1[j * 3 + 2];
                float gate = sigmoidf_(M2) * 0.25f;
                st[j * 160 +            lane] = siluf_(M0) * 0.25f;
                st[j * 160 + 32 +       lane] = siluf_(M1) * 0.25f;
                st[j * 160 + 64 +       lane] = (T1 * y1x + T20) * gate;
                st[j * 160 + 64 + 32 +  lane] = (T1 * y1y + T21) * gate;
                st[j * 160 + 64 + 64 +  lane] = (T1 * y1z + T22) * gate;
            }
        }
        __syncwarp();

        // 8 edges * 160 floats = 320 float4 -> 10 rounds of warp-wide red.v4
        #pragma unroll
        for (int r = 0; r < 10; r++) {
            int g = r * 32 + lane;          // float4 index
            int j = g / 40;
            int q = g - j * 40;
            float4 val = ((const float4*)st)[g];
            int dst = sD[j];
            float* ptr = (q < 16) ? &g_ags[dst * 64 + q * 4]
                                  : &g_agv[dst * 96 + (q - 16) * 4];
            redv4(ptr, val);
        }
        __syncwarp();
    }
}

// ---------------------------------------------------------------------------
// Kernel 3: node post.  8 nodes/block, 96 threads, node-pair f32x2 packing.
// ---------------------------------------------------------------------------
__global__ void __launch_bounds__(96) k_node_post(
    const float* __restrict__ feats,
    const float* __restrict__ attrs,
    const float* __restrict__ Us,   // (64,16)
    const float* __restrict__ Uv,   // (32,16)
    const float* __restrict__ W3s,  // (64,96)
    const float* __restrict__ W3v,  // (32,32)
    const float* __restrict__ SCs,  // (64,16,96)
    const float* __restrict__ SCv,  // (32,16,32)
    float* __restrict__ out)
{
    extern __shared__ float sm[];
    float* cS2    = sm;          // 8192:  [(p*1024+k)*2+h]
    float* cV2    = sm + 8192;   // 12288: [((p*3+iv)*512+k)*2+h]
    float* us2    = sm + 20480;  // 512:   [(p*64+u)*2+h]
    float* uv2    = sm + 20992;  // 768:   [((p*3+iv)*32+u)*2+h]
    float* attr_s = sm + 21760;  // 128
    float* sS     = sm + 21888;  // 512
    float* sV     = sm + 22400;  // 768  (feats layout: u*3+i)
    float* gate_s = sm + 23168;  // 256
    // total 23424 floats = 93696 B

    int tid = threadIdx.x;
    int nbase = blockIdx.x * 8;

    for (int i = tid; i < 8 * 160; i += 96) {
        int t = i / 160, c = i % 160;
        float v = feats[(nbase + t) * 160 + c];
        if (c < 64) sS[t * 64 + c] = v; else sV[t * 96 + (c - 64)] = v;
    }
    for (int i = tid; i < 128; i += 96) attr_s[i] = attrs[nbase * 16 + i];
    __syncthreads();

    // pair-interleaved outer-product coefficients
    for (int i = tid; i < 8192; i += 96) {
        int h = i & 1, k = (i >> 1) & 1023, p = i >> 11;
        int t = 2 * p + h, u = k >> 4, v = k & 15;
        cS2[i] = sS[t * 64 + u] * attr_s[t * 16 + v];
    }
    for (int i = tid; i < 12288; i += 96) {
        int h = i & 1, k = (i >> 1) & 511, rest = i >> 10;
        int iv = rest % 3, p = rest / 3;
        int t = 2 * p + h, u = k >> 4, v = k & 15;
        cV2[i] = sV[t * 96 + u * 3 + iv] * attr_s[t * 16 + v];
    }
    for (int i = tid; i < 512; i += 96) {
        int h = i & 1, u = (i >> 1) & 63, p = i >> 7;
        int t = 2 * p + h;
        float d = 0.f;
        #pragma unroll
        for (int v = 0; v < 16; v++) d += attr_s[t * 16 + v] * Us[u * 16 + v];
        us2[i] = g_ags[(nbase + t) * 64 + u] * d * 0.25f;
    }
    for (int i = tid; i < 768; i += 96) {
        int h = i & 1, u = (i >> 1) & 31, rest = i >> 6;
        int iv = rest % 3, p = rest / 3;
        int t = 2 * p + h;
        float d = 0.f;
        #pragma unroll
        for (int v = 0; v < 16; v++) d += attr_s[t * 16 + v] * Uv[u * 16 + v];
        uv2[i] = g_agv[(nbase + t) * 96 + iv * 32 + u] * d * 0.25f;
    }
    __syncthreads();

    // ---- ts: one output column w per thread, 8 nodes as 4 f32x2 pairs ----
    int w = tid;
    u64 a1[4] = {0,0,0,0}, a2[4] = {0,0,0,0};
    const u64* us64 = (const u64*)us2;
    const u64* cs64 = (const u64*)cS2;
    #pragma unroll 8
    for (int u = 0; u < 64; u++) {
        u64 W = pk2(W3s[u * 96 + w]);
        #pragma unroll
        for (int p = 0; p < 4; p++) ff2(a1[p], us64[p * 64 + u], W);
    }
    #pragma unroll 8
    for (int k = 0; k < 1024; k++) {
        u64 W = pk2(SCs[k * 96 + w]);
        #pragma unroll
        for (int p = 0; p < 4; p++) ff2(a2[p], cs64[p * 1024 + k], W);
    }
    float ts[8];
    #pragma unroll
    for (int p = 0; p < 4; p++) {
        float2 x1 = up2(a1[p]), x2 = up2(a2[p]);
        ts[2 * p]     = x1.x * 0.125f + x2.x * 0.03125f;
        ts[2 * p + 1] = x1.y * 0.125f + x2.y * 0.03125f;
    }
    if (w < 64) {
        #pragma unroll
        for (int t = 0; t < 8; t++)
            out[(nbase + t) * 160 + w] = siluf_(ts[t]);
    } else {
        #pragma unroll
        for (int t = 0; t < 8; t++)
            gate_s[t * 32 + (w - 64)] = sigmoidf_(ts[t]);
    }
    __syncthreads();

    // ---- tv: column (wv = tid%32, component iv = tid/32) ----
    int wv = tid & 31, iv = tid >> 5;
    u64 b1[4] = {0,0,0,0}, b2[4] = {0,0,0,0};
    const u64* uv64 = (const u64*)uv2;
    const u64* cv64 = (const u64*)cV2;
    #pragma unroll 8
    for (int u = 0; u < 32; u++) {
        u64 W = pk2(W3v[u * 32 + wv]);
        #pragma unroll
        for (int p = 0; p < 4; p++) ff2(b1[p], uv64[(p * 3 + iv) * 32 + u], W);
    }
    #pragma unroll 8
    for (int k = 0; k < 512; k++) {
        u64 W = pk2(SCv[k * 32 + wv]);
        #pragma unroll
        for (int p = 0; p < 4; p++) ff2(b2[p], cv64[(p * 3 + iv) * 512 + k], W);
    }
    const float isv  = 0.17677669529663687f;  // 1/sqrt(32)
    const float isvn = 0.044194173824159220f; // 1/sqrt(512)
    #pragma unroll
    for (int p = 0; p < 4; p++) {
        float2 x1 = up2(b1[p]), x2 = up2(b2[p]);
        float tv0 = x1.x * isv + x2.x * isvn;
        float tv1 = x1.y * isv + x2.y * isvn;
        out[(nbase + 2 * p)     * 160 + 64 + wv * 3 + iv] = tv0 * gate_s[(2 * p)     * 32 + wv];
        out[(nbase + 2 * p + 1) * 160 + 64 + wv * 3 + iv] = tv1 * gate_s[(2 * p + 1) * 32 + wv];
    }
}

// ---------------------------------------------------------------------------
extern "C" void kernel_launch(void* const* d_in, const int* in_sizes, int n_in,
                              void* d_out, int out_size)
{
    const float* node_feats = (const float*)d_in[0];
    const float* node_attrs = (const float*)d_in[1];
    const float* edge_attrs = (const float*)d_in[2];
    const float* edge_emb   = (const float*)d_in[3];
    const float* W1s        = (const float*)d_in[4];
    const float* W1v        = (const float*)d_in[5];
    const float* mw0        = (const float*)d_in[6];
    const float* mw1        = (const float*)d_in[7];
    const float* W2s        = (const float*)d_in[8];
    const float* W2v        = (const float*)d_in[9];
    const float* Us         = (const float*)d_in[10];
    const float* Uv         = (const float*)d_in[11];
    const float* W3s        = (const float*)d_in[12];
    const float* W3v        = (const float*)d_in[13];
    const float* SCs        = (const float*)d_in[14];
    const float* SCv        = (const float*)d_in[15];
    const int*   ei         = (const int*)  d_in[16];
    float* out = (float*)d_out;

    k_node_pre<<<6250, 256>>>(node_feats, W1s, W1v);

    cudaFuncSetAttribute(k_edge, cudaFuncAttributeMaxDynamicSharedMemorySize, 105472);
    k_edge<<<592, 192, 105472>>>(edge_attrs, edge_emb, mw0, mw1, W2s, W2v, ei);

    cudaFuncSetAttribute(k_node_post, cudaFuncAttributeMaxDynamicSharedMemorySize, 94208);
    k_node_post<<<6250, 96, 93696>>>(node_feats, node_attrs, Us, Uv, W3s, W3v,
                                     SCs, SCv, out);
}

// round 4
// speedup vs baseline: 1.3467x; 1.3168x over previous
#include <cuda_runtime.h>
#include <math.h>

#define NN 50000
#define NE 800000

__device__ float g_s1 [NN * 64];   // s @ W1_s / 8                  [n][c]
__device__ float g_v1 [NN * 96];   // v . W1_v / sqrt(32)           [n][i*32+u]
__device__ float g_ags[NN * 64];   // scalar aggregate              [n][c]
__device__ float g_agv[NN * 96];   // vector aggregate              [n][i*32+u]

typedef unsigned long long u64;

__device__ __forceinline__ float sigmoidf_(float x) { return 1.0f / (1.0f + __expf(-x)); }
__device__ __forceinline__ float siluf_(float x)    { return x / (1.0f + __expf(-x)); }

__device__ __forceinline__ u64 pk2(float x) {
    u64 r; asm("mov.b64 %0, {%1, %1};" : "=l"(r) : "f"(x)); return r;
}
__device__ __forceinline__ float2 up2(u64 v) {
    float2 r; asm("mov.b64 {%0, %1}, %2;" : "=f"(r.x), "=f"(r.y) : "l"(v)); return r;
}
__device__ __forceinline__ void ff2(u64& d, u64 a, u64 b) {
    asm("fma.rn.f32x2 %0, %1, %2, %0;" : "+l"(d) : "l"(a), "l"(b));
}
__device__ __forceinline__ void redf(float* p, float v) {
    asm volatile("red.global.add.f32 [%0], %1;" :: "l"(p), "f"(v) : "memory");
}

// ---------------------------------------------------------------------------
// Kernel 1: node pre-transform (one warp per node) + zero aggregates
// ---------------------------------------------------------------------------
__global__ void __launch_bounds__(256) k_node_pre(
    const float* __restrict__ feats,
    const float* __restrict__ W1s,
    const float* __restrict__ W1v)
{
    __shared__ float sW1s[64 * 64];
    __shared__ float sW1v[32 * 32];
    __shared__ float stage[8][160];

    int tid = threadIdx.x;
    {
        int gidx = blockIdx.x * 256 + tid;
        float4 z = make_float4(0.f, 0.f, 0.f, 0.f);
        if (gidx < NN * 16) ((float4*)g_ags)[gidx] = z;
        if (gidx < NN * 24) ((float4*)g_agv)[gidx] = z;
    }
    for (int i = tid; i < 4096; i += 256) sW1s[i] = W1s[i];
    for (int i = tid; i < 1024; i += 256) sW1v[i] = W1v[i];
    __syncthreads();

    int warp = tid >> 5, lane = tid & 31;
    int n = blockIdx.x * 8 + warp;
    if (n >= NN) return;

    #pragma unroll
    for (int j = 0; j < 5; j++)
        stage[warp][lane * 5 + j] = feats[n * 160 + lane * 5 + j];
    __syncwarp();

    float a0 = 0.f, a1 = 0.f;
    #pragma unroll 8
    for (int u = 0; u < 64; u++) {
        float su = stage[warp][u];
        a0 += su * sW1s[u * 64 + lane];
        a1 += su * sW1s[u * 64 + 32 + lane];
    }
    g_s1[n * 64 + lane]      = a0 * 0.125f;
    g_s1[n * 64 + 32 + lane] = a1 * 0.125f;

    float b0 = 0.f, b1 = 0.f, b2 = 0.f;
    #pragma unroll 8
    for (int u = 0; u < 32; u++) {
        float wv = sW1v[u * 32 + lane];
        const float* vp = &stage[warp][64 + u * 3];
        b0 += vp[0] * wv; b1 += vp[1] * wv; b2 += vp[2] * wv;
    }
    const float sv = 0.17677669529663687f;
    g_v1[n * 96 +      lane] = b0 * sv;
    g_v1[n * 96 + 32 + lane] = b1 * sv;
    g_v1[n * 96 + 64 + lane] = b2 * sv;
}

// ---------------------------------------------------------------------------
// Kernel 2: edge messages. 8 warps/block, 4 edges/warp, conflict-free staging,
// in-lane gating, direct register->RED scatter.
// ---------------------------------------------------------------------------
#define K2_WARPS 8
#define K2_EPW   4

__global__ void __launch_bounds__(256) k_edge(
    const float* __restrict__ ea,   // edge_attrs  (E,4)
    const float* __restrict__ emb,  // edge_embedding (E,8)
    const float* __restrict__ mw0,  // (8,8)
    const float* __restrict__ mw1,  // (8,192)
    const float* __restrict__ W2s,  // (96,96)
    const float* __restrict__ W2v,  // (96,32)
    const int*   __restrict__ ei)   // (2,E)
{
    extern __shared__ float sm[];
    float* sW2s = sm;                  // 9216
    float* sW2v = sm + 9216;           // 3072
    float* sMw0 = sm + 12288;          // 64
    float* sMw1 = sm + 12352;          // 1536
    float* sStg = sm + 13888;          // 8 warps * 1024

    int tid = threadIdx.x;
    for (int i = tid; i < 9216; i += 256) sW2s[i] = W2s[i];
    for (int i = tid; i < 3072; i += 256) sW2v[i] = W2v[i];
    for (int i = tid; i < 64;   i += 256) sMw0[i] = mw0[i];
    for (int i = tid; i < 1536; i += 256) sMw1[i] = mw1[i];
    __syncthreads();

    int warp = tid >> 5, lane = tid & 31;
    float* stg = sStg + warp * 1024;   // A:[0,384) B:[384,640) C:[640,1024)

    const float is8  = 0.35355339059327373f;  // 1/sqrt(8)
    const float is96 = 0.10206207261596575f;  // 1/sqrt(96)
    const float is3  = 0.57735026918962576f;  // 1/sqrt(3)

    // grid 1250 * 8 warps * 4 edges = 40000 per iteration; 20 exact iterations
    long long stride = (long long)gridDim.x * K2_WARPS * K2_EPW;
    for (long long e0 = (long long)(blockIdx.x * K2_WARPS + warp) * K2_EPW;
         e0 < NE; e0 += stride) {

        int   dsts[K2_EPW];
        float y1x[K2_EPW], y1y[K2_EPW], y1z[K2_EPW];

        // ---- phase 1: build staged messages for 4 edges ----
        #pragma unroll
        for (int j = 0; j < K2_EPW; j++) {
            int e = (int)e0 + j;
            int src = ei[e];
            dsts[j] = ei[NE + e];

            float4 yv = ((const float4*)ea)[e];
            float Y0 = yv.x;
            y1x[j] = yv.y; y1y[j] = yv.z; y1z[j] = yv.w;

            float h[8];
            {
                float4 em0 = ((const float4*)emb)[e * 2 + 0];
                float4 em1 = ((const float4*)emb)[e * 2 + 1];
                float em[8] = {em0.x, em0.y, em0.z, em0.w, em1.x, em1.y, em1.z, em1.w};
                #pragma unroll
                for (int q = 0; q < 8; q++) {
                    float t = 0.f;
                    #pragma unroll
                    for (int k = 0; k < 8; k++) t += em[k] * sMw0[k * 8 + q];
                    h[q] = siluf_(t * is8);
                }
            }
            float wa = 0.f, wb = 0.f, wc = 0.f, wd = 0.f, we = 0.f, wf = 0.f;
            #pragma unroll
            for (int q = 0; q < 8; q++) {
                float hq = h[q]; const float* r = &sMw1[q * 192];
                wa += hq * r[lane];       wb += hq * r[32 + lane];
                wc += hq * r[64 + lane];  wd += hq * r[96 + lane];
                we += hq * r[128 + lane]; wf += hq * r[160 + lane];
            }
            wa *= is8; wb *= is8; wc *= is8; wd *= is8; we *= is8; wf *= is8;

            float se0 = g_s1[src * 64 + lane];
            float se1 = g_s1[src * 64 + 32 + lane];
            float vx  = g_v1[src * 96 +      lane];
            float vy  = g_v1[src * 96 + 32 + lane];
            float vz  = g_v1[src * 96 + 64 + lane];

            // conflict-free: lane-stride-1 stores
            stg[j * 96 +      lane] = wa * se0 * Y0;
            stg[j * 96 + 32 + lane] = wb * se1 * Y0;
            stg[j * 96 + 64 + lane] = wf * (vx * y1x[j] + vy * y1y[j] + vz * y1z[j]) * is3;
            stg[384 + j * 64 +      lane] = wc * se0;
            stg[384 + j * 64 + 32 + lane] = wd * se1;
            float q0 = we * Y0;
            stg[640 + j * 96 +      lane] = q0 * vx;
            stg[640 + j * 96 + 32 + lane] = q0 * vy;
            stg[640 + j * 96 + 64 + lane] = q0 * vz;
        }
        __syncwarp();

        // ---- phase 2: scalar matvecs, weights amortized over 4 edges ----
        float aS0[4], aS1[4], aS2[4], aT1[4], aCx[4], aCy[4], aCz[4];
        #pragma unroll
        for (int j = 0; j < 4; j++) {
            aS0[j] = aS1[j] = aS2[j] = 0.f;
            aT1[j] = aCx[j] = aCy[j] = aCz[j] = 0.f;
        }

        #pragma unroll 4
        for (int u = 0; u < 96; u++) {
            float w0 = sW2s[u * 96 + lane];
            float w1 = sW2s[u * 96 + 32 + lane];
            float w2 = sW2s[u * 96 + 64 + lane];
            #pragma unroll
            for (int j = 0; j < 4; j++) {
                float a = stg[j * 96 + u];
                aS0[j] += a * w0; aS1[j] += a * w1; aS2[j] += a * w2;
            }
        }
        #pragma unroll 4
        for (int u = 0; u < 64; u++) {
            float wv = sW2v[u * 32 + lane];
            #pragma unroll
            for (int j = 0; j < 4; j++) aT1[j] += stg[384 + j * 64 + u] * wv;
        }
        #pragma unroll 4
        for (int u = 0; u < 32; u++) {
            float wv = sW2v[(64 + u) * 32 + lane];
            #pragma unroll
            for (int j = 0; j < 4; j++) {
                aCx[j] += stg[640 + j * 96 +      u] * wv;
                aCy[j] += stg[640 + j * 96 + 32 + u] * wv;
                aCz[j] += stg[640 + j * 96 + 64 + u] * wv;
            }
        }
        __syncwarp();   // staging reads done before next-iter overwrite

        // ---- phase 3: in-lane gate + direct coalesced RED scatter ----
        #pragma unroll
        for (int j = 0; j < 4; j++) {
            int dst = dsts[j];
            float M0 = aS0[j] * is96, M1 = aS1[j] * is96, M2 = aS2[j] * is96;
            float gate = sigmoidf_(M2) * 0.25f;
            float t1 = aT1[j] * is96;
            redf(&g_ags[dst * 64 +      lane], siluf_(M0) * 0.25f);
            redf(&g_ags[dst * 64 + 32 + lane], siluf_(M1) * 0.25f);
            redf(&g_agv[dst * 96 +      lane], (t1 * y1x[j] + aCx[j] * is96) * gate);
            redf(&g_agv[dst * 96 + 32 + lane], (t1 * y1y[j] + aCy[j] * is96) * gate);
            redf(&g_agv[dst * 96 + 64 + lane], (t1 * y1z[j] + aCz[j] * is96) * gate);
        }
    }
}

// ---------------------------------------------------------------------------
// Kernel 3: node post. 8 nodes/block, 192 threads: ts half + tv half run
// concurrently; f32x2 node-pair packing.
// ---------------------------------------------------------------------------
__global__ void __launch_bounds__(192) k_node_post(
    const float* __restrict__ feats,
    const float* __restrict__ attrs,
    const float* __restrict__ Us,   // (64,16)
    const float* __restrict__ Uv,   // (32,16)
    const float* __restrict__ W3s,  // (64,96)
    const float* __restrict__ W3v,  // (32,32)
    const float* __restrict__ SCs,  // (64,16,96)
    const float* __restrict__ SCv,  // (32,16,32)
    float* __restrict__ out)
{
    extern __shared__ float sm[];
    float* cS2    = sm;          // 8192:  [(p*1024+k)*2+h]
    float* cV2    = sm + 8192;   // 12288: [((p*3+iv)*512+k)*2+h]
    float* us2    = sm + 20480;  // 512:   [(p*64+u)*2+h]
    float* uv2    = sm + 20992;  // 768:   [((p*3+iv)*32+u)*2+h]
    float* attr_s = sm + 21760;  // 128
    float* sS     = sm + 21888;  // 512
    float* sV     = sm + 22400;  // 768
    float* gate_s = sm + 23168;  // 256
    // total 23424 floats = 93696 B

    int tid = threadIdx.x;
    int nbase = blockIdx.x * 8;

    for (int i = tid; i < 8 * 160; i += 192) {
        int t = i / 160, c = i % 160;
        float v = feats[(nbase + t) * 160 + c];
        if (c < 64) sS[t * 64 + c] = v; else sV[t * 96 + (c - 64)] = v;
    }
    for (int i = tid; i < 128; i += 192) attr_s[i] = attrs[nbase * 16 + i];
    __syncthreads();

    for (int i = tid; i < 8192; i += 192) {
        int h = i & 1, k = (i >> 1) & 1023, p = i >> 11;
        int t = 2 * p + h, u = k >> 4, v = k & 15;
        cS2[i] = sS[t * 64 + u] * attr_s[t * 16 + v];
    }
    for (int i = tid; i < 12288; i += 192) {
        int h = i & 1, k = (i >> 1) & 511, rest = i >> 10;
        int iv = rest % 3, p = rest / 3;
        int t = 2 * p + h, u = k >> 4, v = k & 15;
        cV2[i] = sV[t * 96 + u * 3 + iv] * attr_s[t * 16 + v];
    }
    for (int i = tid; i < 512; i += 192) {
        int h = i & 1, u = (i >> 1) & 63, p = i >> 7;
        int t = 2 * p + h;
        float d = 0.f;
        #pragma unroll
        for (int v = 0; v < 16; v++) d += attr_s[t * 16 + v] * Us[u * 16 + v];
        us2[i] = g_ags[(nbase + t) * 64 + u] * d * 0.25f;
    }
    for (int i = tid; i < 768; i += 192) {
        int h = i & 1, u = (i >> 1) & 31, rest = i >> 6;
        int iv = rest % 3, p = rest / 3;
        int t = 2 * p + h;
        float d = 0.f;
        #pragma unroll
        for (int v = 0; v < 16; v++) d += attr_s[t * 16 + v] * Uv[u * 16 + v];
        uv2[i] = g_agv[(nbase + t) * 96 + iv * 32 + u] * d * 0.25f;
    }
    __syncthreads();

    int half = tid / 96;
    int r    = tid % 96;

    if (half == 0) {
        // ---- ts: column w = r, 8 nodes as 4 f32x2 pairs ----
        int w = r;
        u64 a1[4] = {0,0,0,0}, a2[4] = {0,0,0,0};
        const u64* us64 = (const u64*)us2;
        const u64* cs64 = (const u64*)cS2;
        #pragma unroll 8
        for (int u = 0; u < 64; u++) {
            u64 W = pk2(W3s[u * 96 + w]);
            #pragma unroll
            for (int p = 0; p < 4; p++) ff2(a1[p], us64[p * 64 + u], W);
        }
        #pragma unroll 8
        for (int k = 0; k < 1024; k++) {
            u64 W = pk2(SCs[k * 96 + w]);
            #pragma unroll
            for (int p = 0; p < 4; p++) ff2(a2[p], cs64[p * 1024 + k], W);
        }
        float ts[8];
        #pragma unroll
        for (int p = 0; p < 4; p++) {
            float2 x1 = up2(a1[p]), x2 = up2(a2[p]);
            ts[2 * p]     = x1.x * 0.125f + x2.x * 0.03125f;
            ts[2 * p + 1] = x1.y * 0.125f + x2.y * 0.03125f;
        }
        if (w < 64) {
            #pragma unroll
            for (int t = 0; t < 8; t++)
                out[(nbase + t) * 160 + w] = siluf_(ts[t]);
        } else {
            #pragma unroll
            for (int t = 0; t < 8; t++)
                gate_s[t * 32 + (w - 64)] = sigmoidf_(ts[t]);
        }
        __syncthreads();
    } else {
        // ---- tv: column (wv = r%32, component iv = r/32), concurrent ----
        int wv = r & 31, iv = r >> 5;
        u64 b1[4] = {0,0,0,0}, b2[4] = {0,0,0,0};
        const u64* uv64 = (const u64*)uv2;
        const u64* cv64 = (const u64*)cV2;
        #pragma unroll 8
        for (int u = 0; u < 32; u++) {
            u64 W = pk2(W3v[u * 32 + wv]);
            #pragma unroll
            for (int p = 0; p < 4; p++) ff2(b1[p], uv64[(p * 3 + iv) * 32 + u], W);
        }
        #pragma unroll 8
        for (int k = 0; k < 512; k++) {
            u64 W = pk2(SCv[k * 32 + wv]);
            #pragma unroll
            for (int p = 0; p < 4; p++) ff2(b2[p], cv64[(p * 3 + iv) * 512 + k], W);
        }
        __syncthreads();   // wait for gate_s from ts half

        const float isv  = 0.17677669529663687f;  // 1/sqrt(32)
        const float isvn = 0.044194173824159220f; // 1/sqrt(512)
        #pragma unroll
        for (int p = 0; p < 4; p++) {
            float2 x1 = up2(b1[p]), x2 = up2(b2[p]);
            float tv0 = x1.x * isv + x2.x * isvn;
            float tv1 = x1.y * isv + x2.y * isvn;
            out[(nbase + 2 * p)     * 160 + 64 + wv * 3 + iv] = tv0 * gate_s[(2 * p)     * 32 + wv];
            out[(nbase + 2 * p + 1) * 160 + 64 + wv * 3 + iv] = tv1 * gate_s[(2 * p + 1) * 32 + wv];
        }
    }
}

// ---------------------------------------------------------------------------
extern "C" void kernel_launch(void* const* d_in, const int* in_sizes, int n_in,
                              void* d_out, int out_size)
{
    const float* node_feats = (const float*)d_in[0];
    const float* node_attrs = (const float*)d_in[1];
    const float* edge_attrs = (const float*)d_in[2];
    const float* edge_emb   = (const float*)d_in[3];
    const float* W1s        = (const float*)d_in[4];
    const float* W1v        = (const float*)d_in[5];
    const float* mw0        = (const float*)d_in[6];
    const float* mw1        = (const float*)d_in[7];
    const float* W2s        = (const float*)d_in[8];
    const float* W2v        = (const float*)d_in[9];
    const float* Us         = (const float*)d_in[10];
    const float* Uv         = (const float*)d_in[11];
    const float* W3s        = (const float*)d_in[12];
    const float* W3v        = (const float*)d_in[13];
    const float* SCs        = (const float*)d_in[14];
    const float* SCv        = (const float*)d_in[15];
    const int*   ei         = (const int*)  d_in[16];
    float* out = (float*)d_out;

    k_node_pre<<<6250, 256>>>(node_feats, W1s, W1v);

    // smem: (13888 + 8*1024) floats = 88320 B
    cudaFuncSetAttribute(k_edge, cudaFuncAttributeMaxDynamicSharedMemorySize, 88320);
    k_edge<<<1250, 256, 88320>>>(edge_attrs, edge_emb, mw0, mw1, W2s, W2v, ei);

    cudaFuncSetAttribute(k_node_post, cudaFuncAttributeMaxDynamicSharedMemorySize, 94208);
    k_node_post<<<6250, 192, 93696>>>(node_feats, node_attrs, Us, Uv, W3s, W3v,
                                      SCs, SCv, out);
}

// round 5
// speedup vs baseline: 1.7890x; 1.3284x over previous
#include <cuda_runtime.h>
#include <math.h>

#define NN 50000
#define NE 800000

__device__ float g_s1 [NN * 64];   // s @ W1_s / 8                  [n][c]
__device__ float g_v1 [NN * 96];   // v . W1_v / sqrt(32)           [n][i*32+u]
__device__ float g_ags[NN * 64];   // scalar aggregate              [n][c]
__device__ float g_agv[NN * 96];   // vector aggregate              [n][i*32+u]

typedef unsigned long long u64;

__device__ __forceinline__ float sigmoidf_(float x) { return 1.0f / (1.0f + __expf(-x)); }
__device__ __forceinline__ float siluf_(float x)    { return x / (1.0f + __expf(-x)); }

__device__ __forceinline__ u64 pk2(float x) {
    u64 r; asm("mov.b64 %0, {%1, %1};" : "=l"(r) : "f"(x)); return r;
}
__device__ __forceinline__ u64 pkab(float a, float b) {
    u64 r; asm("mov.b64 %0, {%1, %2};" : "=l"(r) : "f"(a), "f"(b)); return r;
}
__device__ __forceinline__ float2 up2(u64 v) {
    float2 r; asm("mov.b64 {%0, %1}, %2;" : "=f"(r.x), "=f"(r.y) : "l"(v)); return r;
}
__device__ __forceinline__ void ff2(u64& d, u64 a, u64 b) {
    asm("fma.rn.f32x2 %0, %1, %2, %0;" : "+l"(d) : "l"(a), "l"(b));
}
__device__ __forceinline__ void redf(float* p, float v) {
    asm volatile("red.global.add.f32 [%0], %1;" :: "l"(p), "f"(v) : "memory");
}

// ---------------------------------------------------------------------------
// Kernel 1: node pre-transform (one warp per node) + zero aggregates
// ---------------------------------------------------------------------------
__global__ void __launch_bounds__(256) k_node_pre(
    const float* __restrict__ feats,
    const float* __restrict__ W1s,
    const float* __restrict__ W1v)
{
    __shared__ float sW1s[64 * 64];
    __shared__ float sW1v[32 * 32];
    __shared__ float stage[8][160];

    int tid = threadIdx.x;
    {
        int gidx = blockIdx.x * 256 + tid;
        float4 z = make_float4(0.f, 0.f, 0.f, 0.f);
        if (gidx < NN * 16) ((float4*)g_ags)[gidx] = z;
        if (gidx < NN * 24) ((float4*)g_agv)[gidx] = z;
    }
    for (int i = tid; i < 4096; i += 256) sW1s[i] = W1s[i];
    for (int i = tid; i < 1024; i += 256) sW1v[i] = W1v[i];
    __syncthreads();

    int warp = tid >> 5, lane = tid & 31;
    int n = blockIdx.x * 8 + warp;
    if (n >= NN) return;

    #pragma unroll
    for (int j = 0; j < 5; j++)
        stage[warp][lane * 5 + j] = feats[n * 160 + lane * 5 + j];
    __syncwarp();

    float a0 = 0.f, a1 = 0.f;
    #pragma unroll 8
    for (int u = 0; u < 64; u++) {
        float su = stage[warp][u];
        a0 += su * sW1s[u * 64 + lane];
        a1 += su * sW1s[u * 64 + 32 + lane];
    }
    g_s1[n * 64 + lane]      = a0 * 0.125f;
    g_s1[n * 64 + 32 + lane] = a1 * 0.125f;

    float b0 = 0.f, b1 = 0.f, b2 = 0.f;
    #pragma unroll 8
    for (int u = 0; u < 32; u++) {
        float wv = sW1v[u * 32 + lane];
        const float* vp = &stage[warp][64 + u * 3];
        b0 += vp[0] * wv; b1 += vp[1] * wv; b2 += vp[2] * wv;
    }
    const float sv = 0.17677669529663687f;
    g_v1[n * 96 +      lane] = b0 * sv;
    g_v1[n * 96 + 32 + lane] = b1 * sv;
    g_v1[n * 96 + 64 + lane] = b2 * sv;
}

// ---------------------------------------------------------------------------
// Kernel 2: edge messages. 8 warps/block (forced 2 blocks/SM), 6 edges/warp
// as 3 interleaved pairs; f32x2 matvecs; STS.64/LDS.64 conflict-free staging.
// ---------------------------------------------------------------------------
#define K2_WARPS 8
#define K2_EPW   6

__global__ void __launch_bounds__(256, 2) k_edge(
    const float* __restrict__ ea,   // edge_attrs  (E,4)
    const float* __restrict__ emb,  // edge_embedding (E,8)
    const float* __restrict__ mw0,  // (8,8)
    const float* __restrict__ mw1,  // (8,192)
    const float* __restrict__ W2s,  // (96,96)
    const float* __restrict__ W2v,  // (96,32)
    const int*   __restrict__ ei)   // (2,E)
{
    extern __shared__ float sm[];
    float* sW2s = sm;                  // 9216
    float* sW2v = sm + 9216;           // 3072
    float* sMw0 = sm + 12288;          // 64
    float* sMw1 = sm + 12352;          // 1536
    float* sStg = sm + 13888;          // 8 warps * 1536 floats

    int tid = threadIdx.x;
    for (int i = tid; i < 9216; i += 256) sW2s[i] = W2s[i];
    for (int i = tid; i < 3072; i += 256) sW2v[i] = W2v[i];
    for (int i = tid; i < 64;   i += 256) sMw0[i] = mw0[i];
    for (int i = tid; i < 1536; i += 256) sMw1[i] = mw1[i];
    __syncthreads();

    int warp = tid >> 5, lane = tid & 31;
    float* stg = sStg + warp * 1536;
    u64* A64 = (u64*)stg;           // [p*96 + c], 288 u64
    u64* B64 = (u64*)(stg + 576);   // [p*64 + c], 192 u64
    u64* C64 = (u64*)(stg + 960);   // [p*96 + c], 288 u64

    const float is8  = 0.35355339059327373f;  // 1/sqrt(8)
    const float is96 = 0.10206207261596575f;  // 1/sqrt(96)
    const float is3  = 0.57735026918962576f;  // 1/sqrt(3)

    long long stride = (long long)gridDim.x * K2_WARPS * K2_EPW;
    for (long long e0 = (long long)(blockIdx.x * K2_WARPS + warp) * K2_EPW;
         e0 < NE; e0 += stride) {

        int   dsts[K2_EPW];
        float y1x[K2_EPW], y1y[K2_EPW], y1z[K2_EPW];

        // prefetch indices for the whole group
        int srcs[K2_EPW];
        #pragma unroll
        for (int j = 0; j < K2_EPW; j++) {
            int e = (int)e0 + j;
            int ec = (e < NE) ? e : (NE - 1);
            srcs[j] = ei[ec];
            dsts[j] = ei[NE + ec];
        }

        // ---- phase 1: build pair-packed staged messages ----
        #pragma unroll
        for (int p = 0; p < 3; p++) {
            float buf[2][8];
            #pragma unroll
            for (int h = 0; h < 2; h++) {
                int j = 2 * p + h;
                int e = (int)e0 + j;
                float valid = (e < NE) ? 1.0f : 0.0f;
                int ec = (e < NE) ? e : (NE - 1);
                int src = srcs[j];

                // gathers issued first (overlap with MLP below)
                float se0 = g_s1[src * 64 + lane];
                float se1 = g_s1[src * 64 + 32 + lane];
                float vx  = g_v1[src * 96 +      lane];
                float vy  = g_v1[src * 96 + 32 + lane];
                float vz  = g_v1[src * 96 + 64 + lane];

                float4 yv = ((const float4*)ea)[ec];
                float Y0 = yv.x * valid;
                float yx = yv.y * valid, yy = yv.z * valid, yz = yv.w * valid;
                y1x[j] = yx; y1y[j] = yy; y1z[j] = yz;

                float hh[8];
                {
                    float4 em0 = ((const float4*)emb)[ec * 2 + 0];
                    float4 em1 = ((const float4*)emb)[ec * 2 + 1];
                    float em[8] = {em0.x, em0.y, em0.z, em0.w,
                                   em1.x, em1.y, em1.z, em1.w};
                    #pragma unroll
                    for (int q = 0; q < 8; q++) {
                        float t = 0.f;
                        #pragma unroll
                        for (int k = 0; k < 8; k++) t += em[k] * sMw0[k * 8 + q];
                        hh[q] = siluf_(t * is8);
                    }
                }
                float wa = 0.f, wb = 0.f, wc = 0.f, wd = 0.f, we = 0.f, wf = 0.f;
                #pragma unroll
                for (int q = 0; q < 8; q++) {
                    float hq = hh[q]; const float* r = &sMw1[q * 192];
                    wa += hq * r[lane];       wb += hq * r[32 + lane];
                    wc += hq * r[64 + lane];  wd += hq * r[96 + lane];
                    we += hq * r[128 + lane]; wf += hq * r[160 + lane];
                }
                wa *= is8; wb *= is8; wc *= is8; wd *= is8; we *= is8; wf *= is8;

                buf[h][0] = wa * se0 * Y0;
                buf[h][1] = wb * se1 * Y0;
                buf[h][2] = wf * (vx * yx + vy * yy + vz * yz) * is3;
                buf[h][3] = wc * se0;
                buf[h][4] = wd * se1;
                float q0 = we * Y0;
                buf[h][5] = q0 * vx;
                buf[h][6] = q0 * vy;
                buf[h][7] = q0 * vz;
            }
            // conflict-free pair stores (lane stride 8B)
            A64[p * 96 +      lane] = pkab(buf[0][0], buf[1][0]);
            A64[p * 96 + 32 + lane] = pkab(buf[0][1], buf[1][1]);
            A64[p * 96 + 64 + lane] = pkab(buf[0][2], buf[1][2]);
            B64[p * 64 +      lane] = pkab(buf[0][3], buf[1][3]);
            B64[p * 64 + 32 + lane] = pkab(buf[0][4], buf[1][4]);
            C64[p * 96 +      lane] = pkab(buf[0][5], buf[1][5]);
            C64[p * 96 + 32 + lane] = pkab(buf[0][6], buf[1][6]);
            C64[p * 96 + 64 + lane] = pkab(buf[0][7], buf[1][7]);
        }
        __syncwarp();

        // ---- phase 2: f32x2 matvecs, weights amortized over 6 edges ----
        u64 aS0[3], aS1[3], aS2[3], aB[3], aCx[3], aCy[3], aCz[3];
        #pragma unroll
        for (int p = 0; p < 3; p++) {
            aS0[p] = aS1[p] = aS2[p] = 0ULL;
            aB[p] = aCx[p] = aCy[p] = aCz[p] = 0ULL;
        }

        #pragma unroll 2
        for (int u = 0; u < 96; u++) {
            u64 W0 = pk2(sW2s[u * 96 + lane]);
            u64 W1 = pk2(sW2s[u * 96 + 32 + lane]);
            u64 W2 = pk2(sW2s[u * 96 + 64 + lane]);
            #pragma unroll
            for (int p = 0; p < 3; p++) {
                u64 a = A64[p * 96 + u];
                ff2(aS0[p], a, W0);
                ff2(aS1[p], a, W1);
                ff2(aS2[p], a, W2);
            }
        }
        #pragma unroll 2
        for (int u = 0; u < 64; u++) {
            u64 W = pk2(sW2v[u * 32 + lane]);
            #pragma unroll
            for (int p = 0; p < 3; p++) ff2(aB[p], B64[p * 64 + u], W);
        }
        #pragma unroll 2
        for (int u = 0; u < 32; u++) {
            u64 W = pk2(sW2v[(64 + u) * 32 + lane]);
            #pragma unroll
            for (int p = 0; p < 3; p++) {
                ff2(aCx[p], C64[p * 96 +      u], W);
                ff2(aCy[p], C64[p * 96 + 32 + u], W);
                ff2(aCz[p], C64[p * 96 + 64 + u], W);
            }
        }
        __syncwarp();   // staging reads done before next-iter overwrite

        // ---- phase 3: gate + direct coalesced RED scatter ----
        #pragma unroll
        for (int p = 0; p < 3; p++) {
            float2 m0 = up2(aS0[p]), m1 = up2(aS1[p]), m2 = up2(aS2[p]);
            float2 t1 = up2(aB[p]);
            float2 cx = up2(aCx[p]), cy = up2(aCy[p]), cz = up2(aCz[p]);
            #pragma unroll
            for (int h = 0; h < 2; h++) {
                int j = 2 * p + h;
                int dst = dsts[j];
                float M0 = (h ? m0.y : m0.x) * is96;
                float M1 = (h ? m1.y : m1.x) * is96;
                float M2 = (h ? m2.y : m2.x) * is96;
                float T1 = (h ? t1.y : t1.x) * is96;
                float Cx = (h ? cx.y : cx.x) * is96;
                float Cy = (h ? cy.y : cy.x) * is96;
                float Cz = (h ? cz.y : cz.x) * is96;
                float gate = sigmoidf_(M2) * 0.25f;
                redf(&g_ags[dst * 64 +      lane], siluf_(M0) * 0.25f);
                redf(&g_ags[dst * 64 + 32 + lane], siluf_(M1) * 0.25f);
                redf(&g_agv[dst * 96 +      lane], (T1 * y1x[j] + Cx) * gate);
                redf(&g_agv[dst * 96 + 32 + lane], (T1 * y1y[j] + Cy) * gate);
                redf(&g_agv[dst * 96 + 64 + lane], (T1 * y1z[j] + Cz) * gate);
            }
        }
    }
}

// ---------------------------------------------------------------------------
// Kernel 3: node post. 8 nodes/block, 192 threads; ts half + tv half run
// concurrently; f32x2 node-pair packing.
// ---------------------------------------------------------------------------
__global__ void __launch_bounds__(192, 2) k_node_post(
    const float* __restrict__ feats,
    const float* __restrict__ attrs,
    const float* __restrict__ Us,   // (64,16)
    const float* __restrict__ Uv,   // (32,16)
    const float* __restrict__ W3s,  // (64,96)
    const float* __restrict__ W3v,  // (32,32)
    const float* __restrict__ SCs,  // (64,16,96)
    const float* __restrict__ SCv,  // (32,16,32)
    float* __restrict__ out)
{
    extern __shared__ float sm[];
    float* cS2    = sm;          // 8192
    float* cV2    = sm + 8192;   // 12288
    float* us2    = sm + 20480;  // 512
    float* uv2    = sm + 20992;  // 768
    float* attr_s = sm + 21760;  // 128
    float* sS     = sm + 21888;  // 512
    float* sV     = sm + 22400;  // 768
    float* gate_s = sm + 23168;  // 256

    int tid = threadIdx.x;
    int nbase = blockIdx.x * 8;

    for (int i = tid; i < 8 * 160; i += 192) {
        int t = i / 160, c = i % 160;
        float v = feats[(nbase + t) * 160 + c];
        if (c < 64) sS[t * 64 + c] = v; else sV[t * 96 + (c - 64)] = v;
    }
    for (int i = tid; i < 128; i += 192) attr_s[i] = attrs[nbase * 16 + i];
    __syncthreads();

    for (int i = tid; i < 8192; i += 192) {
        int h = i & 1, k = (i >> 1) & 1023, p = i >> 11;
        int t = 2 * p + h, u = k >> 4, v = k & 15;
        cS2[i] = sS[t * 64 + u] * attr_s[t * 16 + v];
    }
    for (int i = tid; i < 12288; i += 192) {
        int h = i & 1, k = (i >> 1) & 511, rest = i >> 10;
        int iv = rest % 3, p = rest / 3;
        int t = 2 * p + h, u = k >> 4, v = k & 15;
        cV2[i] = sV[t * 96 + u * 3 + iv] * attr_s[t * 16 + v];
    }
    for (int i = tid; i < 512; i += 192) {
        int h = i & 1, u = (i >> 1) & 63, p = i >> 7;
        int t = 2 * p + h;
        float d = 0.f;
        #pragma unroll
        for (int v = 0; v < 16; v++) d += attr_s[t * 16 + v] * Us[u * 16 + v];
        us2[i] = g_ags[(nbase + t) * 64 + u] * d * 0.25f;
    }
    for (int i = tid; i < 768; i += 192) {
        int h = i & 1, u = (i >> 1) & 31, rest = i >> 6;
        int iv = rest % 3, p = rest / 3;
        int t = 2 * p + h;
        float d = 0.f;
        #pragma unroll
        for (int v = 0; v < 16; v++) d += attr_s[t * 16 + v] * Uv[u * 16 + v];
        uv2[i] = g_agv[(nbase + t) * 96 + iv * 32 + u] * d * 0.25f;
    }
    __syncthreads();

    int half = tid / 96;
    int r    = tid % 96;

    if (half == 0) {
        int w = r;
        u64 a1[4] = {0,0,0,0}, a2[4] = {0,0,0,0};
        const u64* us64 = (const u64*)us2;
        const u64* cs64 = (const u64*)cS2;
        #pragma unroll 8
        for (int u = 0; u < 64; u++) {
            u64 W = pk2(W3s[u * 96 + w]);
            #pragma unroll
            for (int p = 0; p < 4; p++) ff2(a1[p], us64[p * 64 + u], W);
        }
        #pragma unroll 8
        for (int k = 0; k < 1024; k++) {
            u64 W = pk2(SCs[k * 96 + w]);
            #pragma unroll
            for (int p = 0; p < 4; p++) ff2(a2[p], cs64[p * 1024 + k], W);
        }
        float ts[8];
        #pragma unroll
        for (int p = 0; p < 4; p++) {
            float2 x1 = up2(a1[p]), x2 = up2(a2[p]);
            ts[2 * p]     = x1.x * 0.125f + x2.x * 0.03125f;
            ts[2 * p + 1] = x1.y * 0.125f + x2.y * 0.03125f;
        }
        if (w < 64) {
            #pragma unroll
            for (int t = 0; t < 8; t++)
                out[(nbase + t) * 160 + w] = siluf_(ts[t]);
        } else {
            #pragma unroll
            for (int t = 0; t < 8; t++)
                gate_s[t * 32 + (w - 64)] = sigmoidf_(ts[t]);
        }
        __syncthreads();
    } else {
        int wv = r & 31, iv = r >> 5;
        u64 b1[4] = {0,0,0,0}, b2[4] = {0,0,0,0};
        const u64* uv64 = (const u64*)uv2;
        const u64* cv64 = (const u64*)cV2;
        #pragma unroll 8
        for (int u = 0; u < 32; u++) {
            u64 W = pk2(W3v[u * 32 + wv]);
            #pragma unroll
            for (int p = 0; p < 4; p++) ff2(b1[p], uv64[(p * 3 + iv) * 32 + u], W);
        }
        #pragma unroll 8
        for (int k = 0; k < 512; k++) {
            u64 W = pk2(SCv[k * 32 + wv]);
            #pragma unroll
            for (int p = 0; p < 4; p++) ff2(b2[p], cv64[(p * 3 + iv) * 512 + k], W);
        }
        __syncthreads();   // wait for gate_s from ts half

        const float isv  = 0.17677669529663687f;  // 1/sqrt(32)
        const float isvn = 0.044194173824159220f; // 1/sqrt(512)
        #pragma unroll
        for (int p = 0; p < 4; p++) {
            float2 x1 = up2(b1[p]), x2 = up2(b2[p]);
            float tv0 = x1.x * isv + x2.x * isvn;
            float tv1 = x1.y * isv + x2.y * isvn;
            out[(nbase + 2 * p)     * 160 + 64 + wv * 3 + iv] = tv0 * gate_s[(2 * p)     * 32 + wv];
            out[(nbase + 2 * p + 1) * 160 + 64 + wv * 3 + iv] = tv1 * gate_s[(2 * p + 1) * 32 + wv];
        }
    }
}

// ---------------------------------------------------------------------------
extern "C" void kernel_launch(void* const* d_in, const int* in_sizes, int n_in,
                              void* d_out, int out_size)
{
    const float* node_feats = (const float*)d_in[0];
    const float* node_attrs = (const float*)d_in[1];
    const float* edge_attrs = (const float*)d_in[2];
    const float* edge_emb   = (const float*)d_in[3];
    const float* W1s        = (const float*)d_in[4];
    const float* W1v        = (const float*)d_in[5];
    const float* mw0        = (const float*)d_in[6];
    const float* mw1        = (const float*)d_in[7];
    const float* W2s        = (const float*)d_in[8];
    const float* W2v        = (const float*)d_in[9];
    const float* Us         = (const float*)d_in[10];
    const float* Uv         = (const float*)d_in[11];
    const float* W3s        = (const float*)d_in[12];
    const float* W3v        = (const float*)d_in[13];
    const float* SCs        = (const float*)d_in[14];
    const float* SCv        = (const float*)d_in[15];
    const int*   ei         = (const int*)  d_in[16];
    float* out = (float*)d_out;

    k_node_pre<<<6250, 256>>>(node_feats, W1s, W1v);

    // smem: (13888 + 8*1536) floats = 104704 B
    cudaFuncSetAttribute(k_edge, cudaFuncAttributeMaxDynamicSharedMemorySize, 104704);
    k_edge<<<1250, 256, 104704>>>(edge_attrs, edge_emb, mw0, mw1, W2s, W2v, ei);

    cudaFuncSetAttribute(k_node_post, cudaFuncAttributeMaxDynamicSharedMemorySize, 94208);
    k_node_post<<<6250, 192, 93696>>>(node_feats, node_attrs, Us, Uv, W3s, W3v,
                                      SCs, SCv, out);
}